// round 6
// baseline (speedup 1.0000x reference)
#include <cuda_runtime.h>

#define L 8
#define A 4
#define D 256
#define SEQ 16384

// ---------------- device scratch (no allocations allowed) ----------------
__device__ float g_P[L * A * D];       // probs[l][c][j] = softmax(hash_emb[l,c,:])[j]
__device__ float g_S[L * A];           // sig[l][c] = sigmoid(sign_logits[l,c])
__device__ unsigned char g_seq8[SEQ];  // sequence values 0..3

// ---------------- kernel 0: pack sequence ----------------
__global__ void pack_seq_k(const int* __restrict__ seq) {
    int i = blockIdx.x * blockDim.x + threadIdx.x;
    if (i < SEQ) g_seq8[i] = (unsigned char)(seq[i] & 3);
}

// ---------------- kernel 1: literal softmax + sigmoid ----------------
__global__ void precompute_lit_k(const float* __restrict__ hash_emb,
                                 const float* __restrict__ sign_logits) {
    int b = blockIdx.x;  // l*A + c
    int t = threadIdx.x;

    __shared__ float sh[D];

    float x = hash_emb[b * D + t];
    sh[t] = x;
    __syncthreads();
    for (int o = 128; o > 0; o >>= 1) {
        if (t < o) sh[t] = fmaxf(sh[t], sh[t + o]);
        __syncthreads();
    }
    float mx = sh[0];
    __syncthreads();
    float e = expf(x - mx);
    sh[t] = e;
    __syncthreads();
    for (int o = 128; o > 0; o >>= 1) {
        if (t < o) sh[t] += sh[t + o];
        __syncthreads();
    }
    float sum = sh[0];
    g_P[b * D + t] = e / sum;
    if (t == 0) g_S[b] = 1.0f / (1.0f + expf(-sign_logits[b]));
}

// ---------------- kernel 2: LITERAL time-domain scan (Tp and Tm separately) ----------------
// 1024 threads: j = t & 255, q = t >> 8 in {0..3}. q handles levels q+1 and q+5.
// Double-buffered Tp/Tm levels 1..8 in smem. Level 0: Tp = delta(j==0), Tm = 0 (constant).
__global__ void __launch_bounds__(1024, 1) scan_lit_k(float* __restrict__ out) {
    __shared__ float Tp[2][L][D];   // 16 KB
    __shared__ float Tm[2][L][D];   // 16 KB

    int t = threadIdx.x;
    int j = t & 255;
    int q = t >> 8;

    for (int i = t; i < 2 * L * D; i += 1024) {
        ((float*)Tp)[i] = 0.0f;
        ((float*)Tm)[i] = 0.0f;
    }
    __syncthreads();

    int cur = 0;

    for (int i = 0; i < SEQ; ++i) {
        int c = (int)g_seq8[i];
        float fi = (float)(i + 1);

        float stp[2], stm[2];
        int   lev[2] = {q + 1, q + 5};

#pragma unroll
        for (int h = 0; h < 2; ++h) {
            int p = lev[h];
            float ap = 0.0f, am = 0.0f;
            if (p == 1) {
                // conv(delta@0, P) = P[j]; conv(0, P) = 0
                ap = __ldg(&g_P[(0 * A + c) * D + j]);
                am = 0.0f;
            } else {
                const float* __restrict__ row = &g_P[((p - 1) * A + c) * D];
                const float* __restrict__ Up = Tp[cur][p - 2];
                const float* __restrict__ Um = Tm[cur][p - 2];
#pragma unroll 4
                for (int s4 = 0; s4 < D; s4 += 4) {
                    float4 pv = __ldg((const float4*)(row + s4));
                    int i0 = (j - s4) & 255, i1 = (j - s4 - 1) & 255;
                    int i2 = (j - s4 - 2) & 255, i3 = (j - s4 - 3) & 255;
                    ap = fmaf(Up[i0], pv.x, ap); am = fmaf(Um[i0], pv.x, am);
                    ap = fmaf(Up[i1], pv.y, ap); am = fmaf(Um[i1], pv.y, am);
                    ap = fmaf(Up[i2], pv.z, ap); am = fmaf(Um[i2], pv.z, am);
                    ap = fmaf(Up[i3], pv.w, ap); am = fmaf(Um[i3], pv.w, am);
                }
            }
            stp[h] = ap;
            stm[h] = am;
        }

        int nxt = cur ^ 1;
#pragma unroll
        for (int h = 0; h < 2; ++h) {
            int p = lev[h];
            float pf = (float)p;
            float z = (pf <= fi) ? (pf / fi) : 0.0f;
            float sg = __ldg(&g_S[(p - 1) * A + c]);
            float up = sg * stp[h] + (1.0f - sg) * stm[h];
            float um = sg * stm[h] + (1.0f - sg) * stp[h];
            float op = Tp[cur][p - 1][j];
            float om = Tm[cur][p - 1][j];
            Tp[nxt][p - 1][j] = (1.0f - z) * op + z * up;
            Tm[nxt][p - 1][j] = (1.0f - z) * om + z * um;
        }
        __syncthreads();
        cur = nxt;
    }

    if (t < D) out[t] = Tp[cur][L - 1][t] - Tm[cur][L - 1][t];
}

// ---------------- launch ----------------
extern "C" void kernel_launch(void* const* d_in, const int* in_sizes, int n_in,
                              void* d_out, int out_size) {
    const int* seq = nullptr;
    const float* hash_emb = nullptr;
    const float* sign_logits = nullptr;
    for (int i = 0; i < n_in; ++i) {
        if (in_sizes[i] == SEQ)            seq = (const int*)d_in[i];
        else if (in_sizes[i] == L * A * D) hash_emb = (const float*)d_in[i];
        else if (in_sizes[i] == L * A)     sign_logits = (const float*)d_in[i];
    }
    if (!seq)         seq = (const int*)d_in[0];
    if (!hash_emb)    hash_emb = (const float*)d_in[1];
    if (!sign_logits) sign_logits = (const float*)d_in[2];

    float* out = (float*)d_out;

    pack_seq_k<<<SEQ / 256, 256>>>(seq);
    precompute_lit_k<<<L * A, D>>>(hash_emb, sign_logits);
    scan_lit_k<<<1, 1024>>>(out);
}

// round 7
// speedup vs baseline: 3.1331x; 3.1331x over previous
#include <cuda_runtime.h>

#define L 8
#define A 4
#define D 256
#define SEQ 16384
#define NCHUNK 4
#define CJ (D / NCHUNK)   // 64 threads / CTA
#define NS 64             // ring slots (power of 2)

// ---------------- device scratch (no allocations allowed) ----------------
__device__ float g_P[L * A * D];       // probs[l][c][j]
__device__ float g_S[L * A];           // sigmoid(sign_logits)
__device__ unsigned char g_seq8[SEQ];  // sequence values 0..3
__device__ float g_ring[L][NS][2][D];  // level lv's (Tp,Tm) per step slot  (1 MB)
__device__ int g_wflag[L][NCHUNK];     // producer: last step written
__device__ int g_pflag[L][NCHUNK];     // reader (level lv): last step staged from ring[lv-1]

// ---------------- kernel 0: pack sequence (verbatim R6) ----------------
__global__ void pack_seq_k(const int* __restrict__ seq) {
    int i = blockIdx.x * blockDim.x + threadIdx.x;
    if (i < SEQ) g_seq8[i] = (unsigned char)(seq[i] & 3);
}

// ---------------- kernel 0b: reset flags (per launch; graph-safe) ----------------
__global__ void init_flags_k() {
    int i = threadIdx.x;
    if (i < L * NCHUNK) {
        ((int*)g_wflag)[i] = -1;
        ((int*)g_pflag)[i] = -1;
    }
}

// ---------------- kernel 1: literal softmax + sigmoid (verbatim R6) ----------------
__global__ void precompute_lit_k(const float* __restrict__ hash_emb,
                                 const float* __restrict__ sign_logits) {
    int b = blockIdx.x;  // l*A + c
    int t = threadIdx.x;

    __shared__ float sh[D];

    float x = hash_emb[b * D + t];
    sh[t] = x;
    __syncthreads();
    for (int o = 128; o > 0; o >>= 1) {
        if (t < o) sh[t] = fmaxf(sh[t], sh[t + o]);
        __syncthreads();
    }
    float mx = sh[0];
    __syncthreads();
    float e = expf(x - mx);
    sh[t] = e;
    __syncthreads();
    for (int o = 128; o > 0; o >>= 1) {
        if (t < o) sh[t] += sh[t + o];
        __syncthreads();
    }
    float sum = sh[0];
    g_P[b * D + t] = e / sum;
    if (t == 0) g_S[b] = 1.0f / (1.0f + expf(-sign_logits[b]));
}

// ---------------- cp.async helpers ----------------
__device__ __forceinline__ void cp_async16(void* smem_dst, const void* gmem_src) {
    unsigned int saddr = (unsigned int)__cvta_generic_to_shared(smem_dst);
    asm volatile("cp.async.ca.shared.global [%0], [%1], 16;" :: "r"(saddr), "l"(gmem_src));
}
__device__ __forceinline__ void cp_async_commit() {
    asm volatile("cp.async.commit_group;");
}
__device__ __forceinline__ void cp_async_wait0() {
    asm volatile("cp.async.wait_group 0;");
}

// ---------------- kernel 2: SYSTOLIC literal scan ----------------
// 32 CTAs: blockIdx.x = lv*NCHUNK + ck; level p = lv+1; j = ck*CJ + tj.
// Arithmetic per (step, level, j) is copied VERBATIM from the passing R6 kernel:
// same fmaf conv chain (s ascending, float4 probs), same update expressions.
__global__ void __launch_bounds__(CJ, 1) scan_sys_k(float* __restrict__ out) {
    const int lv = blockIdx.x >> 2;      // 0..7
    const int ck = blockIdx.x & 3;       // 0..3
    const int tj = threadIdx.x;          // 0..63
    const int j  = ck * CJ + tj;
    const int p  = lv + 1;
    const float pf = (float)p;

    __shared__ unsigned char seq_s[SEQ];     // 16 KB
    __shared__ float4 Ubuf[2][2 * D / 4];    // 4 KB double-buffered prev-level (Tp then Tm)

    // stage the sequence
    for (int i = tj; i < SEQ / 16; i += CJ)
        ((uint4*)seq_s)[i] = ((const uint4*)g_seq8)[i];

    // buffer 0 = zeros (initial state of previous level)
    if (p >= 2) {
        for (int q = tj; q < 2 * D / 4; q += CJ)
            Ubuf[0][q] = make_float4(0.f, 0.f, 0.f, 0.f);
    }
    __syncthreads();

    float tp = 0.0f, tm = 0.0f;

    for (int i = 0; i < SEQ; ++i) {
        const int b = i & 1;
        const int c = (int)seq_s[i];
        const float fi = (float)(i + 1);
        const bool do_prefetch = (p >= 2) && (i + 1 < SEQ);

        // ---- all polling by thread 0, then barrier ----
        if (tj == 0) {
            if (lv < 7 && i >= NS) {
                // backpressure: consumers of our ring must have staged step i-NS
                int need = i - NS;
                for (int k = 0; k < NCHUNK; ++k) {
                    while (*(volatile int*)&g_pflag[lv + 1][k] < need) __nanosleep(64);
                }
            }
            if (do_prefetch) {
                // producer must have written step i
                for (int k = 0; k < NCHUNK; ++k) {
                    while (*(volatile int*)&g_wflag[lv - 1][k] < i) __nanosleep(64);
                }
            }
            __threadfence();
        }
        __syncthreads();

        // ---- kick prefetch of step-i producer data into buffer b^1 ----
        if (do_prefetch) {
            const float4* src = (const float4*)&g_ring[lv - 1][i & (NS - 1)][0][0];
            cp_async16(&Ubuf[b ^ 1][tj],      src + tj);
            cp_async16(&Ubuf[b ^ 1][tj + CJ], src + tj + CJ);
            cp_async_commit();
        }

        // ---- conv (VERBATIM arithmetic from R6) ----
        float ap, am;
        if (p == 1) {
            ap = __ldg(&g_P[(0 * A + c) * D + j]);
            am = 0.0f;
        } else {
            const float* __restrict__ row = &g_P[((p - 1) * A + c) * D];
            const float* __restrict__ Up = (const float*)Ubuf[b];
            const float* __restrict__ Um = ((const float*)Ubuf[b]) + D;
            ap = 0.0f; am = 0.0f;
#pragma unroll 4
            for (int s4 = 0; s4 < D; s4 += 4) {
                float4 pv = __ldg((const float4*)(row + s4));
                int i0 = (j - s4) & 255, i1 = (j - s4 - 1) & 255;
                int i2 = (j - s4 - 2) & 255, i3 = (j - s4 - 3) & 255;
                ap = fmaf(Up[i0], pv.x, ap); am = fmaf(Um[i0], pv.x, am);
                ap = fmaf(Up[i1], pv.y, ap); am = fmaf(Um[i1], pv.y, am);
                ap = fmaf(Up[i2], pv.z, ap); am = fmaf(Um[i2], pv.z, am);
                ap = fmaf(Up[i3], pv.w, ap); am = fmaf(Um[i3], pv.w, am);
            }
        }

        // ---- update (VERBATIM expressions from R6) ----
        {
            float z = (pf <= fi) ? (pf / fi) : 0.0f;
            float sg = __ldg(&g_S[(p - 1) * A + c]);
            float up = sg * ap + (1.0f - sg) * am;
            float um = sg * am + (1.0f - sg) * ap;
            tp = (1.0f - z) * tp + z * up;
            tm = (1.0f - z) * tm + z * um;
        }

        // ---- publish our state for the next level ----
        if (lv < 7) {
            int slot = i & (NS - 1);
            g_ring[lv][slot][0][j] = tp;
            g_ring[lv][slot][1][j] = tm;
            __threadfence();
            __syncthreads();
            if (tj == 0) *(volatile int*)&g_wflag[lv][ck] = i;
        }

        // ---- complete prefetch; free ring slot ----
        if (do_prefetch) {
            cp_async_wait0();
            __syncthreads();
            if (tj == 0) {
                __threadfence();
                *(volatile int*)&g_pflag[lv][ck] = i;   // step-i data staged; slot free
            }
        }
        __syncthreads();
    }

    if (lv == 7) out[j] = tp - tm;
}

// ---------------- launch ----------------
extern "C" void kernel_launch(void* const* d_in, const int* in_sizes, int n_in,
                              void* d_out, int out_size) {
    const int* seq = nullptr;
    const float* hash_emb = nullptr;
    const float* sign_logits = nullptr;
    for (int i = 0; i < n_in; ++i) {
        if (in_sizes[i] == SEQ)            seq = (const int*)d_in[i];
        else if (in_sizes[i] == L * A * D) hash_emb = (const float*)d_in[i];
        else if (in_sizes[i] == L * A)     sign_logits = (const float*)d_in[i];
    }
    if (!seq)         seq = (const int*)d_in[0];
    if (!hash_emb)    hash_emb = (const float*)d_in[1];
    if (!sign_logits) sign_logits = (const float*)d_in[2];

    float* out = (float*)d_out;

    pack_seq_k<<<SEQ / 256, 256>>>(seq);
    init_flags_k<<<1, 64>>>();
    precompute_lit_k<<<L * A, D>>>(hash_emb, sign_logits);
    scan_sys_k<<<L * NCHUNK, CJ>>>(out);
}

// round 8
// speedup vs baseline: 40.2592x; 12.8498x over previous
#include <cuda_runtime.h>

#define L 8
#define A 4
#define D 256
#define SEQ 16384
#define NCH 8                 // j-chunks per level (32 j each)
#define SB 16                 // steps per batch
#define NBATCH (SEQ / SB)     // 1024
#define NSLOT 64              // ring slots (steps), power of 2

// ---------------- device scratch (no allocations allowed) ----------------
__device__ float g_P[L * A * D];        // probs[l][c][s]
__device__ float g_S[L * A];            // sigmoid(sign_logits)
__device__ unsigned char g_seq8[SEQ];   // sequence values 0..3
__device__ float2 g_ring[L][NSLOT][D];  // level lv state (tp,tm) per step slot (1 MB)
__device__ int g_prod[L];               // producer batch counter (8 chunk-CTAs inc per batch)
__device__ int g_cons[L];               // consumer staging counter for ring[lv]

// ---------------- kernel 0: pack sequence (verbatim) ----------------
__global__ void pack_seq_k(const int* __restrict__ seq) {
    int i = blockIdx.x * blockDim.x + threadIdx.x;
    if (i < SEQ) g_seq8[i] = (unsigned char)(seq[i] & 3);
}

// ---------------- kernel 0b: reset counters + zero the "step -1" ring slot ----------------
__global__ void init_flags_k() {
    int t = blockIdx.x * blockDim.x + threadIdx.x;
    if (t < L) { g_prod[t] = 0; g_cons[t] = 0; }
    // zero slot (NSLOT-1) of every level (read as state after step -1 in batch 0)
    for (int q = t; q < L * D; q += gridDim.x * blockDim.x) {
        int lv = q >> 8, j = q & 255;
        g_ring[lv][NSLOT - 1][j] = make_float2(0.f, 0.f);
    }
}

// ---------------- kernel 1: literal softmax + sigmoid (verbatim) ----------------
__global__ void precompute_lit_k(const float* __restrict__ hash_emb,
                                 const float* __restrict__ sign_logits) {
    int b = blockIdx.x;  // l*A + c
    int t = threadIdx.x;

    __shared__ float sh[D];

    float x = hash_emb[b * D + t];
    sh[t] = x;
    __syncthreads();
    for (int o = 128; o > 0; o >>= 1) {
        if (t < o) sh[t] = fmaxf(sh[t], sh[t + o]);
        __syncthreads();
    }
    float mx = sh[0];
    __syncthreads();
    float e = expf(x - mx);
    sh[t] = e;
    __syncthreads();
    for (int o = 128; o > 0; o >>= 1) {
        if (t < o) sh[t] += sh[t + o];
        __syncthreads();
    }
    float sum = sh[0];
    g_P[b * D + t] = e / sum;
    if (t == 0) g_S[b] = 1.0f / (1.0f + expf(-sign_logits[b]));
}

// ---------------- cp.async helpers ----------------
__device__ __forceinline__ void cp_async16(void* smem_dst, const void* gmem_src) {
    unsigned int saddr = (unsigned int)__cvta_generic_to_shared(smem_dst);
    asm volatile("cp.async.ca.shared.global [%0], [%1], 16;" :: "r"(saddr), "l"(gmem_src));
}
__device__ __forceinline__ void cp_async_commit() { asm volatile("cp.async.commit_group;"); }
__device__ __forceinline__ void cp_async_wait0()  { asm volatile("cp.async.wait_group 0;"); }

// ---------------- kernel 2: batched systolic literal scan ----------------
// Grid: 64 CTAs = 8 levels x 8 j-chunks. 512 threads = 16 step-group warps x 32 j-lanes.
// Per batch of SB=16 steps: 16 warps compute 16 independent convs in parallel
// (inputs = previous level's PUBLISHED states, so no intra-batch dependence),
// then warp 0 replays the 16 serial updates in exact time order.
// All per-element fp32 arithmetic is VERBATIM from the passing R6 kernel.
__global__ void __launch_bounds__(512, 1) scan_sys2_k(float* __restrict__ out) {
    const int lv = blockIdx.x >> 3;      // 0..7
    const int ck = blockIdx.x & 7;       // 0..7
    const int tid = threadIdx.x;
    const int lane = tid & 31;
    const int g = tid >> 5;              // step-group (= warp id) 0..15
    const int j = ck * 32 + lane;
    const int p = lv + 1;
    const float pf = (float)p;

    __shared__ float Ps[A][D];           // this level's 4 prob rows (4 KB)
    __shared__ float2 stage[SB][D];      // staged prev-level states (32 KB)
    __shared__ float2 scr[SB][32];       // conv results per (step, j-lane) (4 KB)
    __shared__ unsigned char cb[SB];     // this batch's characters

    // stage P rows (constant for whole kernel); bit-identical to g_P
    for (int q = tid; q < A * D; q += 512)
        ((float*)Ps)[q] = g_P[(p - 1) * A * D + q];
    __syncthreads();

    float tp = 0.0f, tm = 0.0f;          // live state, meaningful on warp 0 only

    for (int b = 0; b < NBATCH; ++b) {
        // ---- polls (thread 0 only), then barrier ----
        if (tid == 0) {
            if (lv > 0) {   // producer must have published batch b
                while (*(volatile int*)&g_prod[lv - 1] < NCH * (b + 1)) {}
            }
            if (lv < 7) {   // consumers must have staged batch b-3 (slot reuse window)
                while (*(volatile int*)&g_cons[lv] < NCH * (b - 2)) {}
            }
            __threadfence();
        }
        __syncthreads();

        // ---- batch characters ----
        if (tid < SB) cb[tid] = g_seq8[b * SB + tid];

        // ---- stage prev-level states for steps b*16-1 .. b*16+14 ----
        if (lv > 0) {
            const int base_step = b * SB - 1;
            for (int idx = tid; idx < SB * 128; idx += 512) {
                int k = idx >> 7, m = idx & 127;                 // 128 x 16B per slot
                int slot = (base_step + k) & (NSLOT - 1);
                cp_async16((char*)&stage[k][0] + m * 16,
                           (const char*)&g_ring[lv - 1][slot][0] + m * 16);
            }
            cp_async_commit();
            cp_async_wait0();
        }
        __syncthreads();

        // staging complete -> release producer's ring slots
        if (lv > 0 && tid == 0) {
            __threadfence();
            atomicAdd(&g_cons[lv - 1], 1);
        }

        // ---- conv for my (step-group g, lane j): step i = b*16+g ----
        // VERBATIM fmaf chain from R6 (same order, same operand values).
        const int c = (int)cb[g];
        float ap, am;
        if (p == 1) {
            ap = Ps[c][j];               // == g_P[(0*A+c)*D+j], bit-identical
            am = 0.0f;
        } else {
            const float* __restrict__ row = &Ps[c][0];
            const float2* __restrict__ Uv = &stage[g][0];
            ap = 0.0f; am = 0.0f;
#pragma unroll 4
            for (int s4 = 0; s4 < D; s4 += 4) {
                float4 pv = *(const float4*)(row + s4);
                int i0 = (j - s4) & 255, i1 = (j - s4 - 1) & 255;
                int i2 = (j - s4 - 2) & 255, i3 = (j - s4 - 3) & 255;
                float2 u0 = Uv[i0], u1 = Uv[i1], u2 = Uv[i2], u3 = Uv[i3];
                ap = fmaf(u0.x, pv.x, ap); am = fmaf(u0.y, pv.x, am);
                ap = fmaf(u1.x, pv.y, ap); am = fmaf(u1.y, pv.y, am);
                ap = fmaf(u2.x, pv.z, ap); am = fmaf(u2.y, pv.z, am);
                ap = fmaf(u3.x, pv.w, ap); am = fmaf(u3.y, pv.w, am);
            }
        }
        scr[g][lane] = make_float2(ap, am);
        __syncthreads();

        // ---- warp 0: serial updates for the 16 steps (VERBATIM expressions) ----
        if (g == 0) {
#pragma unroll
            for (int k = 0; k < SB; ++k) {
                float2 aa = scr[k][lane];
                int cc = (int)cb[k];
                float fi = (float)(b * SB + k + 1);
                float z = (pf <= fi) ? (pf / fi) : 0.0f;
                float sg = __ldg(&g_S[(p - 1) * A + cc]);
                float up = sg * aa.x + (1.0f - sg) * aa.y;
                float um = sg * aa.y + (1.0f - sg) * aa.x;
                tp = (1.0f - z) * tp + z * up;
                tm = (1.0f - z) * tm + z * um;
                if (lv < 7) {
                    int slot = (b * SB + k) & (NSLOT - 1);
                    g_ring[lv][slot][j] = make_float2(tp, tm);
                }
            }
        }
        __syncthreads();

        // publish batch
        if (lv < 7 && tid == 0) {
            __threadfence();
            atomicAdd(&g_prod[lv], 1);
        }
    }

    if (lv == 7 && g == 0) out[j] = tp - tm;
}

// ---------------- launch ----------------
extern "C" void kernel_launch(void* const* d_in, const int* in_sizes, int n_in,
                              void* d_out, int out_size) {
    const int* seq = nullptr;
    const float* hash_emb = nullptr;
    const float* sign_logits = nullptr;
    for (int i = 0; i < n_in; ++i) {
        if (in_sizes[i] == SEQ)            seq = (const int*)d_in[i];
        else if (in_sizes[i] == L * A * D) hash_emb = (const float*)d_in[i];
        else if (in_sizes[i] == L * A)     sign_logits = (const float*)d_in[i];
    }
    if (!seq)         seq = (const int*)d_in[0];
    if (!hash_emb)    hash_emb = (const float*)d_in[1];
    if (!sign_logits) sign_logits = (const float*)d_in[2];

    float* out = (float*)d_out;

    pack_seq_k<<<SEQ / 256, 256>>>(seq);
    init_flags_k<<<4, 256>>>();
    precompute_lit_k<<<L * A, D>>>(hash_emb, sign_logits);
    scan_sys2_k<<<L * NCH, 512>>>(out);
}

// round 9
// speedup vs baseline: 52.3199x; 1.2996x over previous
#include <cuda_runtime.h>

#define L 8
#define A 4
#define D 256
#define SEQ 16384
#define SB 16
#define HALF 8
#define NBATCH (SEQ / SB)   // 1024
#define NSLOT 64            // ring slots (steps)

// ---------------- device scratch ----------------
__device__ float g_P[L * A * D];
__device__ float g_S[L * A];
__device__ unsigned char g_seq8[SEQ];
__device__ float2 g_ring[L][NSLOT][D];        // level state per step slot (1 MB)
__device__ float2 g_scr[L][8][HALF][32];      // sh=1 conv results
__device__ int g_prod[L];                     // +8 per published batch (8 ck updaters)
__device__ int g_cons[L];                     // +16 per staged batch (16 consumer CTAs)
__device__ int g_scrf[L][8];                  // sh=1 -> updater: scr batch ready
__device__ int g_scrc[L][8];                  // updater -> sh=1: scr batch consumed

__device__ __forceinline__ int vload(const int* p) { return *(volatile const int*)p; }

// ---------------- kernel 0: pack sequence (verbatim) ----------------
__global__ void pack_seq_k(const int* __restrict__ seq) {
    int i = blockIdx.x * blockDim.x + threadIdx.x;
    if (i < SEQ) g_seq8[i] = (unsigned char)(seq[i] & 3);
}

// ---------------- kernel 0b: reset counters + zero step(-1) ring slot ----------------
__global__ void init_flags_k() {
    int t = blockIdx.x * blockDim.x + threadIdx.x;
    if (t < L) { g_prod[t] = 0; g_cons[t] = 0; }
    if (t < L * 8) { ((int*)g_scrf)[t] = 0; ((int*)g_scrc)[t] = 0; }
    for (int q = t; q < L * D; q += gridDim.x * blockDim.x) {
        int lv = q >> 8, j = q & 255;
        g_ring[lv][NSLOT - 1][j] = make_float2(0.f, 0.f);
    }
}

// ---------------- kernel 1: literal softmax + sigmoid (verbatim) ----------------
__global__ void precompute_lit_k(const float* __restrict__ hash_emb,
                                 const float* __restrict__ sign_logits) {
    int b = blockIdx.x;
    int t = threadIdx.x;
    __shared__ float sh[D];

    float x = hash_emb[b * D + t];
    sh[t] = x;
    __syncthreads();
    for (int o = 128; o > 0; o >>= 1) {
        if (t < o) sh[t] = fmaxf(sh[t], sh[t + o]);
        __syncthreads();
    }
    float mx = sh[0];
    __syncthreads();
    float e = expf(x - mx);
    sh[t] = e;
    __syncthreads();
    for (int o = 128; o > 0; o >>= 1) {
        if (t < o) sh[t] += sh[t + o];
        __syncthreads();
    }
    float sum = sh[0];
    g_P[b * D + t] = e / sum;
    if (t == 0) g_S[b] = 1.0f / (1.0f + expf(-sign_logits[b]));
}

// ---------------- cp.async (.cg = L1-bypass, L2-fresh) ----------------
__device__ __forceinline__ void cp_async16(void* smem_dst, const void* gmem_src) {
    unsigned int saddr = (unsigned int)__cvta_generic_to_shared(smem_dst);
    asm volatile("cp.async.cg.shared.global [%0], [%1], 16;" :: "r"(saddr), "l"(gmem_src));
}
__device__ __forceinline__ void cp_async_commit() { asm volatile("cp.async.commit_group;"); }
__device__ __forceinline__ void cp_async_wait0()  { asm volatile("cp.async.wait_group 0;"); }

// ---------------- kernel 2: 2-way step-split systolic literal scan ----------------
// 128 CTAs: blockIdx.x = (lv*8 + ck)*2 + sh. 256 threads = 8 step-warps x 32 j-lanes.
// Warp g computes the conv for step i = b*16 + sh*8 + g. sh=0 CTA owns the serial
// update of all 16 steps (sh=1 ships results via g_scr). fp32 arithmetic VERBATIM.
__global__ void __launch_bounds__(256, 1) scan_sys3_k(float* __restrict__ out) {
    const int bid = blockIdx.x;
    const int sh = bid & 1;
    const int ck = (bid >> 1) & 7;
    const int lv = bid >> 4;
    const int tid = threadIdx.x;
    const int lane = tid & 31;
    const int g = tid >> 5;           // 0..7
    const int j = ck * 32 + lane;
    const int p = lv + 1;
    const float pf = (float)p;

    __shared__ float Ps[A][D];                 // 4 KB
    __shared__ float2 stage[2][HALF][D];       // 32 KB double-buffered prev-level states
    __shared__ float2 scr_s[HALF][32];         // 2 KB own conv results (sh=0)
    __shared__ float Ss[A];
    __shared__ unsigned char cbatch[SB];

    for (int q = tid; q < A * D; q += 256)
        ((float*)Ps)[q] = g_P[(p - 1) * A * D + q];
    if (tid < A) Ss[tid] = g_S[(p - 1) * A + tid];
    __syncthreads();

    // prologue: stage batch 0
    if (lv > 0) {
        if (tid == 0) {
            while (vload(&g_prod[lv - 1]) < 8) __nanosleep(32);
            __threadfence();
        }
        __syncthreads();
        const int base = sh * HALF - 1;
        for (int idx = tid; idx < HALF * 128; idx += 256) {
            int k = idx >> 7, m = idx & 127;
            int slot = (base + k) & (NSLOT - 1);
            cp_async16((char*)&stage[0][k][0] + m * 16,
                       (const char*)&g_ring[lv - 1][slot][0] + m * 16);
        }
        cp_async_commit();
        cp_async_wait0();
        __syncthreads();
        if (tid == 0) { __threadfence(); atomicAdd(&g_cons[lv - 1], 1); }
    }

    float tp = 0.0f, tm = 0.0f;   // live state (meaningful on sh=0 warp 0)

    for (int b = 0; b < NBATCH; ++b) {
        const int buf = b & 1;
        if (tid < SB) cbatch[tid] = g_seq8[b * SB + tid];
        __syncthreads();

        // ---- conv for my step (VERBATIM arithmetic) ----
        const int kk = sh * HALF + g;
        const int c = (int)cbatch[kk];
        float ap, am;
        if (p == 1) {
            ap = Ps[c][j];
            am = 0.0f;
        } else {
            const float* __restrict__ row = &Ps[c][0];
            const float2* __restrict__ Uv = &stage[buf][g][0];
            ap = 0.0f; am = 0.0f;
#pragma unroll 4
            for (int s4 = 0; s4 < D; s4 += 4) {
                float4 pv = *(const float4*)(row + s4);
                int i0 = (j - s4) & 255, i1 = (j - s4 - 1) & 255;
                int i2 = (j - s4 - 2) & 255, i3 = (j - s4 - 3) & 255;
                float2 u0 = Uv[i0], u1 = Uv[i1], u2 = Uv[i2], u3 = Uv[i3];
                ap = fmaf(u0.x, pv.x, ap); am = fmaf(u0.y, pv.x, am);
                ap = fmaf(u1.x, pv.y, ap); am = fmaf(u1.y, pv.y, am);
                ap = fmaf(u2.x, pv.z, ap); am = fmaf(u2.y, pv.z, am);
                ap = fmaf(u3.x, pv.w, ap); am = fmaf(u3.y, pv.w, am);
            }
        }

        if (sh == 1) {
            // ---- ship conv results to updater ----
            if (tid == 0) { while (vload(&g_scrc[lv][ck]) < b) __nanosleep(32); }
            __syncthreads();
            g_scr[lv][ck][g][lane] = make_float2(ap, am);
            __threadfence();
            __syncthreads();
            if (tid == 0) *(volatile int*)&g_scrf[lv][ck] = b + 1;

            // next-batch producer poll + prefetch
            if (lv > 0 && b + 1 < NBATCH) {
                if (tid == 0) {
                    while (vload(&g_prod[lv - 1]) < 8 * (b + 2)) __nanosleep(32);
                    __threadfence();
                }
                __syncthreads();
                const int base = (b + 1) * SB + sh * HALF - 1;
                for (int idx = tid; idx < HALF * 128; idx += 256) {
                    int k = idx >> 7, m = idx & 127;
                    int slot = (base + k) & (NSLOT - 1);
                    cp_async16((char*)&stage[buf ^ 1][k][0] + m * 16,
                               (const char*)&g_ring[lv - 1][slot][0] + m * 16);
                }
                cp_async_commit();
                cp_async_wait0();
                __syncthreads();
                if (tid == 0) { __threadfence(); atomicAdd(&g_cons[lv - 1], 1); }
            }
            __syncthreads();
        } else {
            // ---- updater CTA ----
            scr_s[g][lane] = make_float2(ap, am);
            __syncthreads();

            if (tid == 0) {
                if (lv > 0 && b + 1 < NBATCH) {
                    while (vload(&g_prod[lv - 1]) < 8 * (b + 2)) __nanosleep(32);
                }
                if (lv < 7) {
                    while (vload(&g_cons[lv]) < 16 * (b - 2)) __nanosleep(32);
                }
                __threadfence();
            }
            __syncthreads();

            // prefetch next batch (overlaps gather + update)
            if (lv > 0 && b + 1 < NBATCH) {
                const int base = (b + 1) * SB + sh * HALF - 1;
                for (int idx = tid; idx < HALF * 128; idx += 256) {
                    int k = idx >> 7, m = idx & 127;
                    int slot = (base + k) & (NSLOT - 1);
                    cp_async16((char*)&stage[buf ^ 1][k][0] + m * 16,
                               (const char*)&g_ring[lv - 1][slot][0] + m * 16);
                }
                cp_async_commit();
            }

            if (g == 0) {
                // gather partner results
                if (lane == 0) { while (vload(&g_scrf[lv][ck]) < b + 1) __nanosleep(32); }
                __syncwarp();
                __threadfence();
                float2 r[HALF];
#pragma unroll
                for (int k = 0; k < HALF; ++k)
                    r[k] = __ldcg(&g_scr[lv][ck][k][lane]);
                // release scr buffer (store value data-depends on the loads)
                int dep = 0;
#pragma unroll
                for (int k = 0; k < HALF; ++k)
                    dep |= (__float_as_int(r[k].x) & 0);
                if (lane == 0) *(volatile int*)&g_scrc[lv][ck] = (b + 1) | dep;

                // ---- 16 serial updates (VERBATIM expressions) ----
#pragma unroll
                for (int k = 0; k < SB; ++k) {
                    float2 aa = (k < HALF) ? scr_s[k][lane] : r[k - HALF];
                    int cc = (int)cbatch[k];
                    float fi = (float)(b * SB + k + 1);
                    float z = (pf <= fi) ? (pf / fi) : 0.0f;
                    float sg = Ss[cc];
                    float up = sg * aa.x + (1.0f - sg) * aa.y;
                    float um = sg * aa.y + (1.0f - sg) * aa.x;
                    tp = (1.0f - z) * tp + z * up;
                    tm = (1.0f - z) * tm + z * um;
                    if (lv < 7)
                        g_ring[lv][(b * SB + k) & (NSLOT - 1)][j] = make_float2(tp, tm);
                }
                if (lv < 7) {
                    __threadfence();
                    if (lane == 0) atomicAdd(&g_prod[lv], 1);
                }
            }

            if (lv > 0 && b + 1 < NBATCH) cp_async_wait0();
            __syncthreads();
            if (lv > 0 && b + 1 < NBATCH && tid == 0) {
                __threadfence();
                atomicAdd(&g_cons[lv - 1], 1);
            }
            __syncthreads();
        }
    }

    if (lv == 7 && sh == 0 && g == 0) out[j] = tp - tm;
}

// ---------------- launch ----------------
extern "C" void kernel_launch(void* const* d_in, const int* in_sizes, int n_in,
                              void* d_out, int out_size) {
    const int* seq = nullptr;
    const float* hash_emb = nullptr;
    const float* sign_logits = nullptr;
    for (int i = 0; i < n_in; ++i) {
        if (in_sizes[i] == SEQ)            seq = (const int*)d_in[i];
        else if (in_sizes[i] == L * A * D) hash_emb = (const float*)d_in[i];
        else if (in_sizes[i] == L * A)     sign_logits = (const float*)d_in[i];
    }
    if (!seq)         seq = (const int*)d_in[0];
    if (!hash_emb)    hash_emb = (const float*)d_in[1];
    if (!sign_logits) sign_logits = (const float*)d_in[2];

    float* out = (float*)d_out;

    pack_seq_k<<<SEQ / 256, 256>>>(seq);
    init_flags_k<<<4, 256>>>();
    precompute_lit_k<<<L * A, D>>>(hash_emb, sign_logits);
    scan_sys3_k<<<L * 8 * 2, 256>>>(out);
}

// round 10
// speedup vs baseline: 59.0155x; 1.1280x over previous
#include <cuda_runtime.h>

#define L 8
#define A 4
#define D 256
#define SEQ 16384
#define SB 16
#define HALF 8
#define NBATCH (SEQ / SB)   // 1024
#define NSLOT 64            // ring slots (steps)

// ---------------- device scratch ----------------
__device__ float g_P[L * A * D];
__device__ float g_S[L * A];
__device__ unsigned char g_seq8[SEQ];
__device__ float2 g_ring[L][NSLOT][D];          // level state per step slot (1 MB)
__device__ float2 g_scr[L][8][2][HALF][32];     // sh=1 conv results (double-buffered)
__device__ int g_prod[L];                       // +8 per published batch
__device__ int g_cons[L];                       // +16 per staged batch
__device__ int g_scrf[L][8];                    // shipper -> updater: batch ready
__device__ int g_scrc[L][8];                    // updater -> shipper: batch consumed

__device__ __forceinline__ int vload(const int* p)  { return *(volatile const int*)p; }
__device__ __forceinline__ int vloads(const int* p) { return *(volatile const int*)p; }

// ---------------- kernel 0: pack sequence (verbatim) ----------------
__global__ void pack_seq_k(const int* __restrict__ seq) {
    int i = blockIdx.x * blockDim.x + threadIdx.x;
    if (i < SEQ) g_seq8[i] = (unsigned char)(seq[i] & 3);
}

// ---------------- kernel 0b: reset counters + zero step(-1) ring slot ----------------
__global__ void init_flags_k() {
    int t = blockIdx.x * blockDim.x + threadIdx.x;
    if (t < L) { g_prod[t] = 0; g_cons[t] = 0; }
    if (t < L * 8) { ((int*)g_scrf)[t] = 0; ((int*)g_scrc)[t] = 0; }
    for (int q = t; q < L * D; q += gridDim.x * blockDim.x) {
        int lv = q >> 8, j = q & 255;
        g_ring[lv][NSLOT - 1][j] = make_float2(0.f, 0.f);
    }
}

// ---------------- kernel 1: literal softmax + sigmoid (verbatim) ----------------
__global__ void precompute_lit_k(const float* __restrict__ hash_emb,
                                 const float* __restrict__ sign_logits) {
    int b = blockIdx.x;
    int t = threadIdx.x;
    __shared__ float sh[D];

    float x = hash_emb[b * D + t];
    sh[t] = x;
    __syncthreads();
    for (int o = 128; o > 0; o >>= 1) {
        if (t < o) sh[t] = fmaxf(sh[t], sh[t + o]);
        __syncthreads();
    }
    float mx = sh[0];
    __syncthreads();
    float e = expf(x - mx);
    sh[t] = e;
    __syncthreads();
    for (int o = 128; o > 0; o >>= 1) {
        if (t < o) sh[t] += sh[t + o];
        __syncthreads();
    }
    float sum = sh[0];
    g_P[b * D + t] = e / sum;
    if (t == 0) g_S[b] = 1.0f / (1.0f + expf(-sign_logits[b]));
}

// ---------------- cp.async helpers ----------------
__device__ __forceinline__ void cp_async16(void* smem_dst, const void* gmem_src) {
    unsigned int saddr = (unsigned int)__cvta_generic_to_shared(smem_dst);
    asm volatile("cp.async.cg.shared.global [%0], [%1], 16;" :: "r"(saddr), "l"(gmem_src));
}
__device__ __forceinline__ void cp_async_commit() { asm volatile("cp.async.commit_group;"); }
__device__ __forceinline__ void cp_async_wait0()  { asm volatile("cp.async.wait_group 0;"); }

// ---------------- kernel 2: warp-specialized systolic literal scan ----------------
// 128 CTAs = (lv, ck, sh). 288 threads = 8 conv warps (one step each) + 1 control warp.
// Conv warps stream batch-to-batch, throttled only by smem counters; the control
// warp does gather/serial-update/publish (sh=0) or ship (sh=1) plus staging,
// entirely overlapped with the next batch's convolutions.
// All per-element fp32 arithmetic is VERBATIM from the passing R6 kernel.
__global__ void __launch_bounds__(288, 1) scan_sys4_k(float* __restrict__ out) {
    const int bid = blockIdx.x;
    const int sh = bid & 1;
    const int ck = (bid >> 1) & 7;
    const int lv = bid >> 4;
    const int tid = threadIdx.x;
    const int lane = tid & 31;
    const int wid = tid >> 5;           // 0..8
    const int j = ck * 32 + lane;
    const int p = lv + 1;
    const float pf = (float)p;

    __shared__ float Ps[A][D];                 // 4 KB
    __shared__ float Ss[A];
    __shared__ float2 stage[2][HALF][D];       // 32 KB
    __shared__ float2 scr_s[2][HALF][32];      // 4 KB
    __shared__ int cdone[HALF];                // conv-done batch counters
    __shared__ int scr_free;                   // control consumed-through counter
    __shared__ int stage_rdy;                  // staged-through counter

    for (int q = tid; q < A * D; q += 288)
        ((float*)Ps)[q] = g_P[(p - 1) * A * D + q];
    if (tid < A) Ss[tid] = g_S[(p - 1) * A + tid];
    if (tid < HALF) cdone[tid] = 0;
    if (tid == 0) { scr_free = 0; stage_rdy = 0; }
    __syncthreads();

    // ---- prologue: stage batches 0 and 1 ----
    if (lv > 0) {
        for (int w = 0; w < 2; ++w) {
            if (tid == 0) {
                while (vload(&g_prod[lv - 1]) < 8 * (w + 1)) __nanosleep(128);
                __threadfence();
            }
            __syncthreads();
            const int base = w * SB + sh * HALF - 1;
            for (int idx = tid; idx < HALF * 128; idx += 288) {
                int k = idx >> 7, m = idx & 127;
                int slot = (base + k) & (NSLOT - 1);
                cp_async16((char*)&stage[w][k][0] + m * 16,
                           (const char*)&g_ring[lv - 1][slot][0] + m * 16);
            }
            cp_async_commit();
        }
        cp_async_wait0();
        __syncthreads();
        if (tid == 0) { __threadfence(); atomicAdd(&g_cons[lv - 1], 2); }
    }
    if (tid == 0) *(volatile int*)&stage_rdy = (lv == 0) ? (NBATCH + 4) : 2;
    __syncthreads();   // LAST full barrier — roles diverge below

    if (wid < 8) {
        // ================= CONV WARP (step kk = sh*8 + wid) =================
        const int g = wid;
        const int kk = sh * HALF + g;
        for (int b = 0; b < NBATCH; ++b) {
            // wait: stage data for batch b present; scr buffer parity free
            while (vloads(&stage_rdy) < b + 1) __nanosleep(32);
            while (vloads(&scr_free) < b - 1) __nanosleep(32);

            const int c = (int)__ldg(&g_seq8[b * SB + kk]);
            float ap, am;
            if (p == 1) {
                ap = Ps[c][j];
                am = 0.0f;
            } else {
                const float* __restrict__ row = &Ps[c][0];
                const float2* __restrict__ Uv = &stage[b & 1][g][0];
                ap = 0.0f; am = 0.0f;
#pragma unroll 4
                for (int s4 = 0; s4 < D; s4 += 4) {
                    float4 pv = *(const float4*)(row + s4);
                    int i0 = (j - s4) & 255, i1 = (j - s4 - 1) & 255;
                    int i2 = (j - s4 - 2) & 255, i3 = (j - s4 - 3) & 255;
                    float2 u0 = Uv[i0], u1 = Uv[i1], u2 = Uv[i2], u3 = Uv[i3];
                    ap = fmaf(u0.x, pv.x, ap); am = fmaf(u0.y, pv.x, am);
                    ap = fmaf(u1.x, pv.y, ap); am = fmaf(u1.y, pv.y, am);
                    ap = fmaf(u2.x, pv.z, ap); am = fmaf(u2.y, pv.z, am);
                    ap = fmaf(u3.x, pv.w, ap); am = fmaf(u3.y, pv.w, am);
                }
            }
            scr_s[b & 1][g][lane] = make_float2(ap, am);
            __threadfence_block();
            if (lane == 0) *(volatile int*)&cdone[g] = b + 1;
        }
    } else {
        // ================= CONTROL WARP =================
        float tp = 0.0f, tm = 0.0f;
        for (int b = 0; b < NBATCH; ++b) {
            // wait all conv warps done with batch b
            if (lane == 0) {
#pragma unroll
                for (int g2 = 0; g2 < HALF; ++g2)
                    while (vloads(&cdone[g2]) < b + 1) __nanosleep(32);
            }
            __syncwarp();
            __threadfence_block();

            if (sh == 1) {
                // ---- ship conv results to updater ----
                if (lane == 0) { while (vload(&g_scrc[lv][ck]) < b - 1) __nanosleep(64); }
                __syncwarp();
#pragma unroll
                for (int k = 0; k < HALF; ++k)
                    g_scr[lv][ck][b & 1][k][lane] = scr_s[b & 1][k][lane];
                __threadfence();
                if (lane == 0) {
                    *(volatile int*)&g_scrf[lv][ck] = b + 1;
                    *(volatile int*)&scr_free = b + 1;
                }
            } else {
                // ---- updater ----
                if (lane == 0) {
                    if (lv < 7) while (vload(&g_cons[lv]) < 16 * (b - 2)) __nanosleep(64);
                    while (vload(&g_scrf[lv][ck]) < b + 1) __nanosleep(64);
                }
                __syncwarp();
                __threadfence();
                float2 r[HALF];
#pragma unroll
                for (int k = 0; k < HALF; ++k)
                    r[k] = __ldcg(&g_scr[lv][ck][b & 1][k][lane]);

                int4 cw = __ldg((const int4*)&g_seq8[b * SB]);
                const unsigned char* cb = (const unsigned char*)&cw;
#pragma unroll
                for (int k = 0; k < SB; ++k) {
                    float2 aa = (k < HALF) ? scr_s[b & 1][k][lane] : r[k - HALF];
                    int cc = (int)cb[k];
                    float fi = (float)(b * SB + k + 1);
                    float z = (pf <= fi) ? (pf / fi) : 0.0f;
                    float sg = Ss[cc];
                    float up = sg * aa.x + (1.0f - sg) * aa.y;
                    float um = sg * aa.y + (1.0f - sg) * aa.x;
                    tp = (1.0f - z) * tp + z * up;
                    tm = (1.0f - z) * tm + z * um;
                    if (lv < 7)
                        g_ring[lv][(b * SB + k) & (NSLOT - 1)][j] = make_float2(tp, tm);
                }
                if (lv < 7) {
                    __threadfence();
                    if (lane == 0) atomicAdd(&g_prod[lv], 1);
                }
                // releases: all r[k]/scr_s reads consumed above (in-order issue)
                asm volatile("" ::: "memory");
                if (lane == 0) {
                    *(volatile int*)&g_scrc[lv][ck] = b + 1;
                    *(volatile int*)&scr_free = b + 1;
                }
            }

            // ---- stage batch b+2 (overlaps conv of batch b+1) ----
            if (lv > 0 && b + 2 < NBATCH) {
                const int w = b + 2;
                if (lane == 0) {
                    while (vload(&g_prod[lv - 1]) < 8 * (w + 1)) __nanosleep(64);
                    __threadfence();
                }
                __syncwarp();
                const int base = w * SB + sh * HALF - 1;
                for (int idx = lane; idx < HALF * 128; idx += 32) {
                    int k = idx >> 7, m = idx & 127;
                    int slot = (base + k) & (NSLOT - 1);
                    cp_async16((char*)&stage[w & 1][k][0] + m * 16,
                               (const char*)&g_ring[lv - 1][slot][0] + m * 16);
                }
                cp_async_commit();
                cp_async_wait0();
                __threadfence_block();
                if (lane == 0) {
                    __threadfence();
                    atomicAdd(&g_cons[lv - 1], 1);
                    *(volatile int*)&stage_rdy = w + 1;
                }
            }
            __syncwarp();
        }
        if (lv == 7 && sh == 0) out[j] = tp - tm;
    }
}

// ---------------- launch ----------------
extern "C" void kernel_launch(void* const* d_in, const int* in_sizes, int n_in,
                              void* d_out, int out_size) {
    const int* seq = nullptr;
    const float* hash_emb = nullptr;
    const float* sign_logits = nullptr;
    for (int i = 0; i < n_in; ++i) {
        if (in_sizes[i] == SEQ)            seq = (const int*)d_in[i];
        else if (in_sizes[i] == L * A * D) hash_emb = (const float*)d_in[i];
        else if (in_sizes[i] == L * A)     sign_logits = (const float*)d_in[i];
    }
    if (!seq)         seq = (const int*)d_in[0];
    if (!hash_emb)    hash_emb = (const float*)d_in[1];
    if (!sign_logits) sign_logits = (const float*)d_in[2];

    float* out = (float*)d_out;

    pack_seq_k<<<SEQ / 256, 256>>>(seq);
    init_flags_k<<<4, 256>>>();
    precompute_lit_k<<<L * A, D>>>(hash_emb, sign_logits);
    scan_sys4_k<<<L * 8 * 2, 288>>>(out);
}

// round 12
// speedup vs baseline: 79.6375x; 1.3494x over previous
#include <cuda_runtime.h>

#define L 8
#define A 4
#define D 256
#define SEQ 16384
#define SB 16
#define HALF 8
#define NBATCH (SEQ / SB)   // 1024
#define NSLOT 256           // ring steps = 16 batches of elasticity

// ---------------- device scratch ----------------
__device__ float g_P[L * A * D];
__device__ float g_S[L * A];
__device__ unsigned char g_seq8[SEQ];
__device__ float2 g_ring[L][NSLOT][D];          // 4 MB level-state ring
__device__ float2 g_scr[L][8][4][HALF][32];     // shipped conv results (quad buf)
__device__ int g_prod[L];                       // +8 per published batch
__device__ int g_cons[L];                       // +16 per staged batch
__device__ int g_scrf[L][8];                    // shipper -> updater
__device__ int g_scrc[L][8];                    // updater -> shipper

__device__ __forceinline__ int vload(const int* p)  { return *(volatile const int*)p; }

// ---------------- kernel 0: pack sequence (verbatim) ----------------
__global__ void pack_seq_k(const int* __restrict__ seq) {
    int i = blockIdx.x * blockDim.x + threadIdx.x;
    if (i < SEQ) g_seq8[i] = (unsigned char)(seq[i] & 3);
}

// ---------------- kernel 0b: reset counters + zero step(-1) ring slot ----------------
__global__ void init_flags_k() {
    int t = blockIdx.x * blockDim.x + threadIdx.x;
    if (t < L) { g_prod[t] = 0; g_cons[t] = 0; }
    if (t < L * 8) { ((int*)g_scrf)[t] = 0; ((int*)g_scrc)[t] = 0; }
    for (int q = t; q < L * D; q += gridDim.x * blockDim.x) {
        int lv = q >> 8, j = q & 255;
        g_ring[lv][NSLOT - 1][j] = make_float2(0.f, 0.f);
    }
}

// ---------------- kernel 1: literal softmax + sigmoid (verbatim) ----------------
__global__ void precompute_lit_k(const float* __restrict__ hash_emb,
                                 const float* __restrict__ sign_logits) {
    int b = blockIdx.x;
    int t = threadIdx.x;
    __shared__ float sh[D];

    float x = hash_emb[b * D + t];
    sh[t] = x;
    __syncthreads();
    for (int o = 128; o > 0; o >>= 1) {
        if (t < o) sh[t] = fmaxf(sh[t], sh[t + o]);
        __syncthreads();
    }
    float mx = sh[0];
    __syncthreads();
    float e = expf(x - mx);
    sh[t] = e;
    __syncthreads();
    for (int o = 128; o > 0; o >>= 1) {
        if (t < o) sh[t] += sh[t + o];
        __syncthreads();
    }
    float sum = sh[0];
    g_P[b * D + t] = e / sum;
    if (t == 0) g_S[b] = 1.0f / (1.0f + expf(-sign_logits[b]));
}

// ---------------- cp.async helpers ----------------
__device__ __forceinline__ void cp_async16(void* smem_dst, const void* gmem_src) {
    unsigned int saddr = (unsigned int)__cvta_generic_to_shared(smem_dst);
    asm volatile("cp.async.cg.shared.global [%0], [%1], 16;" :: "r"(saddr), "l"(gmem_src));
}
__device__ __forceinline__ void cp_async_commit() { asm volatile("cp.async.commit_group;"); }
__device__ __forceinline__ void cp_async_wait0()  { asm volatile("cp.async.wait_group 0;"); }

// ---------------- kernel 2: deep-buffered warp-specialized systolic scan ----------------
// 128 CTAs = (lv, ck, sh). 320 threads = 8 conv warps + control warp (8) + stager warp (9).
// RING GATE (fixed): stage of batch w reads slots 16w-1..16w+14; slot 16w-1 is
// re-written at batch w+15, so writing batch b requires batch (b-15) staged:
// g_cons >= 16*(b-14).
// All per-element fp32 arithmetic is VERBATIM from the passing R6 kernel.
__global__ void __launch_bounds__(320, 1) scan_sys5_k(float* __restrict__ out) {
    const int bid = blockIdx.x;
    const int sh = bid & 1;
    const int ck = (bid >> 1) & 7;
    const int lv = bid >> 4;
    const int tid = threadIdx.x;
    const int lane = tid & 31;
    const int wid = tid >> 5;           // 0..9
    const int j = ck * 32 + lane;
    const int p = lv + 1;
    const float pf = (float)p;

    __shared__ float Ps[A][D];                 // 4 KB
    __shared__ float Ss[A];
    __shared__ float2 stage[2][HALF][D];       // 32 KB
    __shared__ float2 scr_s[4][HALF][32];      // 8 KB (quad)
    __shared__ int cdone[HALF];
    __shared__ int scr_free;                   // batches consumed by control
    __shared__ int stage_rdy;                  // batches staged

    for (int q = tid; q < A * D; q += 320)
        ((float*)Ps)[q] = g_P[(p - 1) * A * D + q];
    if (tid < A) Ss[tid] = g_S[(p - 1) * A + tid];
    if (tid < HALF) cdone[tid] = 0;
    if (tid == 0) { scr_free = 0; stage_rdy = 0; }
    __syncthreads();

    // ---- prologue: stage batches 0 and 1 (whole CTA) ----
    if (lv > 0) {
        for (int w = 0; w < 2; ++w) {
            if (tid == 0) {
                while (vload(&g_prod[lv - 1]) < 8 * (w + 1)) __nanosleep(128);
                __threadfence();
            }
            __syncthreads();
            const int base = w * SB + sh * HALF - 1;
            for (int idx = tid; idx < HALF * 128; idx += 320) {
                int k = idx >> 7, m = idx & 127;
                int slot = (base + k) & (NSLOT - 1);
                cp_async16((char*)&stage[w][k][0] + m * 16,
                           (const char*)&g_ring[lv - 1][slot][0] + m * 16);
            }
            cp_async_commit();
        }
        cp_async_wait0();
        __syncthreads();
        if (tid == 0) { __threadfence(); atomicAdd(&g_cons[lv - 1], 2); }
    }
    if (tid == 0) *(volatile int*)&stage_rdy = (lv == 0) ? (NBATCH + 4) : 2;
    __syncthreads();   // LAST full barrier

    if (wid < 8) {
        // ================= CONV WARP (step kk = sh*8 + wid) =================
        const int g = wid;
        const int kk = sh * HALF + g;
        for (int b = 0; b < NBATCH; ++b) {
            while (vload(&stage_rdy) < b + 1) __nanosleep(32);
            while (vload(&scr_free) < b - 3) __nanosleep(32);
            __threadfence_block();

            const int c = (int)__ldg(&g_seq8[b * SB + kk]);
            float ap, am;
            if (p == 1) {
                ap = Ps[c][j];
                am = 0.0f;
            } else {
                const float* __restrict__ row = &Ps[c][0];
                const float2* __restrict__ Uv = &stage[b & 1][g][0];
                ap = 0.0f; am = 0.0f;
#pragma unroll 4
                for (int s4 = 0; s4 < D; s4 += 4) {
                    float4 pv = *(const float4*)(row + s4);
                    int i0 = (j - s4) & 255, i1 = (j - s4 - 1) & 255;
                    int i2 = (j - s4 - 2) & 255, i3 = (j - s4 - 3) & 255;
                    float2 u0 = Uv[i0], u1 = Uv[i1], u2 = Uv[i2], u3 = Uv[i3];
                    ap = fmaf(u0.x, pv.x, ap); am = fmaf(u0.y, pv.x, am);
                    ap = fmaf(u1.x, pv.y, ap); am = fmaf(u1.y, pv.y, am);
                    ap = fmaf(u2.x, pv.z, ap); am = fmaf(u2.y, pv.z, am);
                    ap = fmaf(u3.x, pv.w, ap); am = fmaf(u3.y, pv.w, am);
                }
            }
            scr_s[b & 3][g][lane] = make_float2(ap, am);
            __threadfence_block();
            if (lane == 0) *(volatile int*)&cdone[g] = b + 1;
        }
    } else if (wid == 8) {
        // ================= CONTROL WARP =================
        float tp = 0.0f, tm = 0.0f;
        for (int b = 0; b < NBATCH; ++b) {
            // all conv warps done with batch b (parallel poll: lane k watches cdone[k])
            if (lane < HALF) { while (vload(&cdone[lane]) < b + 1) __nanosleep(32); }
            __syncwarp();

            if (sh == 1) {
                // ---- shipper ----
                if (lane == 0) { while (vload(&g_scrc[lv][ck]) < b - 3) __nanosleep(64); }
                __syncwarp();
                __threadfence_block();
                float2 v[HALF];
#pragma unroll
                for (int k = 0; k < HALF; ++k) v[k] = scr_s[b & 3][k][lane];
                // release data-depends on every lane's loads (ballot)
                int dep = 0;
#pragma unroll
                for (int k = 0; k < HALF; ++k)
                    dep |= __float_as_int(v[k].x) | __float_as_int(v[k].y);
                unsigned ball = __ballot_sync(0xFFFFFFFFu, dep != 0x7FC00000);
                if (lane == 0) *(volatile int*)&scr_free = (b + 1) | (int)(ball & 0u);
#pragma unroll
                for (int k = 0; k < HALF; ++k)
                    g_scr[lv][ck][b & 3][k][lane] = v[k];
                __threadfence();
                if (lane == 0) *(volatile int*)&g_scrf[lv][ck] = b + 1;
            } else {
                // ---- updater ----
                if (lane == 0) {
                    while (vload(&g_scrf[lv][ck]) < b + 1) __nanosleep(64);
                    // FIXED gate: writing batch b requires batch (b-15) staged
                    if (lv < 7) while (vload(&g_cons[lv]) < 16 * (b - 14)) __nanosleep(64);
                }
                __syncwarp();
                __threadfence();

                float2 ss[HALF], rr[HALF];
#pragma unroll
                for (int k = 0; k < HALF; ++k) ss[k] = scr_s[b & 3][k][lane];
#pragma unroll
                for (int k = 0; k < HALF; ++k) rr[k] = __ldcg(&g_scr[lv][ck][b & 3][k][lane]);

                // race-free release: flag value data-depends on ALL lanes' loads
                int dep = 0;
#pragma unroll
                for (int k = 0; k < HALF; ++k)
                    dep |= __float_as_int(rr[k].x) | __float_as_int(rr[k].y) |
                           __float_as_int(ss[k].x) | __float_as_int(ss[k].y);
                unsigned ball = __ballot_sync(0xFFFFFFFFu, dep != 0x7FC00000);
                int zero = (int)(ball & 0u);         // always 0, depends on every lane
                if (lane == 0) {
                    *(volatile int*)&scr_free = (b + 1) | zero;
                    *(volatile int*)&g_scrc[lv][ck] = (b + 1) | zero;
                }

                // ---- 16 serial updates (VERBATIM expressions) ----
                int4 cw = __ldg((const int4*)&g_seq8[b * SB]);
                const unsigned char* cb = (const unsigned char*)&cw;
#pragma unroll
                for (int k = 0; k < SB; ++k) {
                    float2 aa = (k < HALF) ? ss[k] : rr[k - HALF];
                    int cc = (int)cb[k];
                    float fi = (float)(b * SB + k + 1);
                    float z = (pf <= fi) ? (pf / fi) : 0.0f;
                    float sg = Ss[cc];
                    float up = sg * aa.x + (1.0f - sg) * aa.y;
                    float um = sg * aa.y + (1.0f - sg) * aa.x;
                    tp = (1.0f - z) * tp + z * up;
                    tm = (1.0f - z) * tm + z * um;
                    if (lv < 7)
                        g_ring[lv][(b * SB + k) & (NSLOT - 1)][j] = make_float2(tp, tm);
                }
                if (lv < 7) {
                    __threadfence();
                    if (lane == 0) atomicAdd(&g_prod[lv], 1);
                }
            }
            __syncwarp();
        }
        if (lv == 7 && sh == 0) out[j] = tp - tm;
    } else {
        // ================= STAGER WARP (lv > 0 only) =================
        if (lv > 0) {
            for (int w = 2; w < NBATCH; ++w) {
                // stage[w&1] free once conv finished batch w-2
                if (lane < HALF) { while (vload(&cdone[lane]) < w - 1) __nanosleep(64); }
                if (lane == 0) {
                    while (vload(&g_prod[lv - 1]) < 8 * (w + 1)) __nanosleep(64);
                    __threadfence();
                }
                __syncwarp();
                const int base = w * SB + sh * HALF - 1;
                for (int idx = lane; idx < HALF * 128; idx += 32) {
                    int k = idx >> 7, m = idx & 127;
                    int slot = (base + k) & (NSLOT - 1);
                    cp_async16((char*)&stage[w & 1][k][0] + m * 16,
                               (const char*)&g_ring[lv - 1][slot][0] + m * 16);
                }
                cp_async_commit();
                cp_async_wait0();
                __threadfence_block();
                if (lane == 0) {
                    __threadfence();
                    atomicAdd(&g_cons[lv - 1], 1);
                    *(volatile int*)&stage_rdy = w + 1;
                }
                __syncwarp();
            }
        }
    }
}

// ---------------- launch ----------------
extern "C" void kernel_launch(void* const* d_in, const int* in_sizes, int n_in,
                              void* d_out, int out_size) {
    const int* seq = nullptr;
    const float* hash_emb = nullptr;
    const float* sign_logits = nullptr;
    for (int i = 0; i < n_in; ++i) {
        if (in_sizes[i] == SEQ)            seq = (const int*)d_in[i];
        else if (in_sizes[i] == L * A * D) hash_emb = (const float*)d_in[i];
        else if (in_sizes[i] == L * A)     sign_logits = (const float*)d_in[i];
    }
    if (!seq)         seq = (const int*)d_in[0];
    if (!hash_emb)    hash_emb = (const float*)d_in[1];
    if (!sign_logits) sign_logits = (const float*)d_in[2];

    float* out = (float*)d_out;

    pack_seq_k<<<SEQ / 256, 256>>>(seq);
    init_flags_k<<<4, 256>>>();
    precompute_lit_k<<<L * A, D>>>(hash_emb, sign_logits);
    scan_sys5_k<<<L * 8 * 2, 320>>>(out);
}